// round 16
// baseline (speedup 1.0000x reference)
#include <cuda_runtime.h>
#include <cuda_bf16.h>
#include <mma.h>
#include <math.h>

using namespace nvcuda;

#define BATCH   256
#define NEI     128
#define NRELS   5000
#define NSUP    32
#define DIM     128
#define TOPK    64
#define NCAND   8192

#define OFF_TN  0
#define OFF_TE  49152
#define OFF_PI  6340608
#define OFF_PN  6389760
#define OFF_AR  6438912

typedef unsigned long long ull;
typedef unsigned int u32;

__device__ float g_best[NRELS];
__device__ u32   g_rank[NRELS];
__device__ float g_relgi[NRELS * 384];
__device__ ull   g_w2ih[128 * 384];              // dup-pair W_ih for relgi
__device__ float g_whhT[128 * 384];              // W_hh^T k-major, tf32-rounded
__device__ float g_gh[BATCH * TOPK * 384];       // GEMM output scratch
__device__ int   g_e[3][BATCH * TOPK];
__device__ int   g_r[3][BATCH * TOPK];
__device__ int   g_p[3][BATCH * TOPK];

__device__ __forceinline__ ull f2pack(float lo, float hi) {
    ull d; asm("mov.b64 %0, {%1, %2};" : "=l"(d) : "f"(lo), "f"(hi)); return d;
}
__device__ __forceinline__ ull f2fma(ull a, ull b, ull c) {
    ull d; asm("fma.rn.f32x2 %0, %1, %2, %3;" : "=l"(d) : "l"(a), "l"(b), "l"(c)); return d;
}
__device__ __forceinline__ u32 ord32(float s) {
    u32 u = __float_as_uint(s);
    return (u & 0x80000000u) ? ~u : (u | 0x80000000u);
}
__device__ __forceinline__ float tanh_hw(float x) {
    float y; asm("tanh.approx.f32 %0, %1;" : "=f"(y) : "f"(x)); return y;
}
__device__ __forceinline__ float sig_hw(float x) {
    return fmaf(tanh_hw(0.5f * x), 0.5f, 0.5f);
}

#define SHN 20
#define LDA 132
#define LDB2 200   // 192-col B slice + pad

// ================= expand_big body (512 threads) =============================
__device__ __forceinline__ void expand_big_body(const int2* __restrict__ edge,
                                                float* __restrict__ out,
                                                int step, int b) {
    __shared__ int s_cur[TOPK];
    __shared__ u32 s_p13[16], s_q13[16];
    __shared__ u32 s_bp, s_bq;
    __shared__ u32 wkeys[TOPK];
    __shared__ u32 s_wn;

    const int tid = threadIdx.x;
    const int wid = tid >> 5, lane = tid & 31;

    if (tid < TOPK) s_cur[tid] = g_e[step - 1][b * TOPK + tid];
    if (tid == 0) s_wn = 0;
    __syncthreads();

    u32 myk[16];
    #pragma unroll
    for (int m = 0; m < 16; ++m) {
        int i = tid + m * 512;
        int c = i >> 7, n = i & 127;
        int2 pr = __ldg(&edge[(long long)s_cur[c] * NEI + n]);
        myk[m] = (g_rank[pr.y] << 13) | (u32)i;
    }

    u32 K = 0;
    #pragma unroll 1
    for (int shift = 24; shift >= 0; shift -= 2) {
        u32 X1 = K | (1u << shift), X2 = K | (2u << shift), X3 = K | (3u << shift);
        u32 c1 = 0, c2 = 0, c3 = 0;
        #pragma unroll
        for (int m = 0; m < 16; ++m) {
            u32 k0 = myk[m];
            c1 += (k0 < X1); c2 += (k0 < X2); c3 += (k0 < X3);
        }
        u32 p = c1 | (c2 << 16);
        u32 q = c3;
        p = __reduce_add_sync(0xffffffffu, p);
        q = __reduce_add_sync(0xffffffffu, q);
        if (lane == 0) { s_p13[wid] = p; s_q13[wid] = q; }
        __syncthreads();
        if (tid < 32) {
            u32 vp = (tid < 16) ? s_p13[tid] : 0u;
            u32 vq = (tid < 16) ? s_q13[tid] : 0u;
            vp = __reduce_add_sync(0xffffffffu, vp);
            vq = __reduce_add_sync(0xffffffffu, vq);
            if (tid == 0) { s_bp = vp; s_bq = vq; }
        }
        __syncthreads();
        u32 n1 = s_bp & 0xffffu, n2 = s_bp >> 16, n3 = s_bq;
        u32 t = (n1 < TOPK) ? ((n2 < TOPK) ? ((n3 < TOPK) ? 3u : 2u) : 1u) : 0u;
        K |= t << shift;
        __syncthreads();
    }

    #pragma unroll
    for (int m = 0; m < 16; ++m) {
        if (myk[m] <= K) {
            u32 p = atomicAdd(&s_wn, 1u);
            wkeys[p] = myk[m];
        }
    }
    __syncthreads();

    if (tid < TOPK) {
        u32 my = wkeys[tid];
        int rank = 0;
        #pragma unroll 8
        for (int t = 0; t < TOPK; ++t) rank += (wkeys[t] < my);
        int i = my & (NCAND - 1);
        int c = i >> 7, n = i & 127;
        int ent = s_cur[c];
        int2 pr = __ldg(&edge[(long long)ent * NEI + n]);
        int j = rank;
        int gidx = b * TOPK + j;
        g_e[step][gidx] = pr.x;
        g_r[step][gidx] = pr.y;
        g_p[step][gidx] = c;
        out[OFF_TN + b * 192 + step * 64 + j] = (float)pr.x;
        if (step == 1) {
            out[OFF_PI + b * 192 + j]       = (float)c;
            out[OFF_PN + b * 192 + 64 + j]  = (float)g_e[0][b * TOPK + c];
            out[OFF_AR + b * 192 + j]       = (float)g_r[0][b * TOPK + c];
        } else {
            out[OFF_PI + b * 192 + 64 + j]  = (float)c;
            out[OFF_PN + b * 192 + 128 + j] = (float)g_e[1][b * TOPK + c];
            out[OFF_AR + b * 192 + 64 + j]  = (float)g_r[1][b * TOPK + c];
            out[OFF_AR + b * 192 + 128 + j] = (float)pr.y;
        }
    }
}

// ================= K1: weight prep || best ===================================
__global__ void __launch_bounds__(512) k1_kernel(const float* __restrict__ wih,
                                                 const float* __restrict__ whh,
                                                 const float* __restrict__ cosm,
                                                 const int* __restrict__ sup) {
    const int bid = blockIdx.x, tid = threadIdx.x;
    if (bid < 96) {
        int idx = bid * 512 + tid;
        int j = idx / 128, k = idx % 128;
        float a = wih[idx];
        g_w2ih[k * 384 + j] = f2pack(a, a);
        g_whhT[k * 384 + j] = wmma::__float_to_tf32(whh[idx]);
    } else {
        __shared__ int ss[NSUP];
        if (tid < NSUP) ss[tid] = sup[tid];
        __syncthreads();
        int r = (bid - 96) * 512 + tid;
        if (r < NRELS) {
            float m = -3.4e38f;
            #pragma unroll
            for (int s = 0; s < NSUP; ++s)
                m = fmaxf(m, cosm[(long long)ss[s] * NRELS + r]);
            g_best[r] = m;
        }
    }
}

// ================= K2: relgi || rank || expand0 (128-thread blocks) ==========
__global__ void __launch_bounds__(128) k2_kernel(const float* __restrict__ rel_emb,
                                                 const float* __restrict__ b_ih,
                                                 const int2* __restrict__ edge,
                                                 const int* __restrict__ query_head,
                                                 float* __restrict__ out) {
    const int bid = blockIdx.x, tid = threadIdx.x;
    if (bid < 313) {
        __shared__ __align__(16) float s_x[128 * SHN];
        const int rb = bid * 16;
        const int d = tid;
        #pragma unroll
        for (int n = 0; n < 16; ++n) {
            int r = rb + n;
            s_x[d * SHN + n] = (r < NRELS) ? __ldg(&rel_emb[r * 128 + d]) : 0.f;
        }
        __syncthreads();
        ull aR[8], aZ[8], aN[8];
        float br = b_ih[d], bz = b_ih[128 + d], bn = b_ih[256 + d];
        #pragma unroll
        for (int m = 0; m < 8; ++m) {
            aR[m] = f2pack(br, br); aZ[m] = f2pack(bz, bz); aN[m] = f2pack(bn, bn);
        }
        const ull* wt = g_w2ih;
        #pragma unroll 4
        for (int k = 0; k < 128; ++k) {
            ull wr2 = __ldg(&wt[k * 384 + d]);
            ull wz2 = __ldg(&wt[k * 384 + 128 + d]);
            ull wn2 = __ldg(&wt[k * 384 + 256 + d]);
            const ulonglong2* row = (const ulonglong2*)&s_x[k * SHN];
            ulonglong2 h0 = row[0], h1 = row[1], h2 = row[2], h3 = row[3];
            aR[0] = f2fma(wr2, h0.x, aR[0]); aR[1] = f2fma(wr2, h0.y, aR[1]);
            aR[2] = f2fma(wr2, h1.x, aR[2]); aR[3] = f2fma(wr2, h1.y, aR[3]);
            aR[4] = f2fma(wr2, h2.x, aR[4]); aR[5] = f2fma(wr2, h2.y, aR[5]);
            aR[6] = f2fma(wr2, h3.x, aR[6]); aR[7] = f2fma(wr2, h3.y, aR[7]);
            aZ[0] = f2fma(wz2, h0.x, aZ[0]); aZ[1] = f2fma(wz2, h0.y, aZ[1]);
            aZ[2] = f2fma(wz2, h1.x, aZ[2]); aZ[3] = f2fma(wz2, h1.y, aZ[3]);
            aZ[4] = f2fma(wz2, h2.x, aZ[4]); aZ[5] = f2fma(wz2, h2.y, aZ[5]);
            aZ[6] = f2fma(wz2, h3.x, aZ[6]); aZ[7] = f2fma(wz2, h3.y, aZ[7]);
            aN[0] = f2fma(wn2, h0.x, aN[0]); aN[1] = f2fma(wn2, h0.y, aN[1]);
            aN[2] = f2fma(wn2, h1.x, aN[2]); aN[3] = f2fma(wn2, h1.y, aN[3]);
            aN[4] = f2fma(wn2, h2.x, aN[4]); aN[5] = f2fma(wn2, h2.y, aN[5]);
            aN[6] = f2fma(wn2, h3.x, aN[6]); aN[7] = f2fma(wn2, h3.y, aN[7]);
        }
        #pragma unroll
        for (int m = 0; m < 8; ++m) {
            float2 vr = *(float2*)&aR[m], vz = *(float2*)&aZ[m], vn = *(float2*)&aN[m];
            int r0 = rb + 2 * m, r1 = r0 + 1;
            if (r0 < NRELS) {
                g_relgi[r0 * 384 + d] = vr.x;
                g_relgi[r0 * 384 + 128 + d] = vz.x;
                g_relgi[r0 * 384 + 256 + d] = vn.x;
            }
            if (r1 < NRELS) {
                g_relgi[r1 * 384 + d] = vr.y;
                g_relgi[r1 * 384 + 128 + d] = vz.y;
                g_relgi[r1 * 384 + 256 + d] = vn.y;
            }
        }
    } else if (bid < 353) {
        __shared__ float tile[128];
        const int r = (bid - 313) * 128 + tid;
        const float mine = (r < NRELS) ? g_best[r] : 3.4e38f;
        u32 cnt = 0;
        for (int base = 0; base < NRELS; base += 128) {
            int t = base + tid;
            tile[tid] = (t < NRELS) ? g_best[t] : -3.4e38f;
            __syncthreads();
            int lim = NRELS - base; if (lim > 128) lim = 128;
            #pragma unroll 8
            for (int u = 0; u < lim; ++u) cnt += (tile[u] > mine);
            __syncthreads();
        }
        if (r < NRELS) g_rank[r] = cnt;
    } else {
        __shared__ __align__(16) ull keys[128];
        __shared__ int s_ent;
        const int b = bid - 353;
        const int i = tid;
        if (i == 0) s_ent = query_head[b];
        __syncthreads();
        const int ent = s_ent;
        int2 pr = __ldg(&edge[(long long)ent * NEI + i]);
        ull mykey = ((ull)ord32(g_best[pr.y]) << 32) | (u32)(127 - i);
        keys[i] = mykey;
        __syncthreads();
        int rank = 0;
        #pragma unroll 8
        for (int t = 0; t < 128; ++t) rank += (keys[t] > mykey);
        if (rank < TOPK) {
            int j = rank;
            int gidx = b * TOPK + j;
            g_e[0][gidx] = pr.x;
            g_r[0][gidx] = pr.y;
            g_p[0][gidx] = 0;
            out[OFF_TN + b * 192 + j] = (float)pr.x;
            out[OFF_PN + b * 192 + j] = (float)ent;
            out[OFF_PI + b * 192 + 128 + j] = (float)j;
        }
    }
}

// ================= K3: expand_big(1) || gru1 (hw-tanh) =======================
__global__ void __launch_bounds__(512) k3_kernel(const int2* __restrict__ edge,
                                                 const float* __restrict__ b_hh,
                                                 float* __restrict__ out) {
    const int bid = blockIdx.x;
    if (bid < 256) {
        expand_big_body(edge, out, 1, bid);
    } else {
        const int idx = (bid - 256) * 512 + threadIdx.x;
        const int d = idx & 127;
        const int k = (idx >> 7) & 63;
        const int b = idx >> 13;
        const int r = g_r[0][b * TOPK + k];
        const float* gi = &g_relgi[r * 384];
        float hr = b_hh[d], hz = b_hh[128 + d], hn = b_hh[256 + d];
        float rg = sig_hw(gi[d] + hr);
        float z  = sig_hw(gi[128 + d] + hz);
        float nn = tanh_hw(fmaf(rg, hn, gi[256 + d]));
        out[OFF_TE + ((b * 3 + 0) * 64 + k) * 128 + d] = (1.f - z) * nn;
    }
}

// ================= expand_big standalone =====================================
__global__ void __launch_bounds__(512) xbig_kernel(const int2* __restrict__ edge,
                                                   float* __restrict__ out, int step) {
    expand_big_body(edge, out, step, blockIdx.x);
}

// ================= gemm: n-split tf32 wmma, double-buffered 16-row B slices ==
// grid (2, BATCH): block = 64 nodes x 192 cols. 384 threads = 12 warps.
// 8 iterations x 1 sync; next slice LDG-prefetched under current MMAs.
__global__ void __launch_bounds__(384, 2) gemm_kernel(const float* __restrict__ out, int step) {
    __shared__ __align__(16) float s_h[64 * LDA];       // 33.8 KB
    __shared__ __align__(16) float s_b[2][16 * LDB2];   // 25.6 KB
    __shared__ int s_p[64];

    const int nh = blockIdx.x;        // n-half: cols [nh*192, nh*192+192)
    const int b  = blockIdx.y;
    const int tid = threadIdx.x;
    if (tid < 64) s_p[tid] = g_p[step][b * TOPK + tid];
    __syncthreads();
    const float* te_prev = &out[OFF_TE + (b * 3 + (step - 1)) * 64 * 128];
    for (int idx = tid; idx < 64 * 128; idx += 384) {
        int n = idx >> 7, d = idx & 127;
        s_h[n * LDA + d] = wmma::__float_to_tf32(te_prev[s_p[n] * 128 + d]);
    }

    const int wid = tid >> 5;
    const int srow = tid / 24;            // staging row 0..15
    const int scol = (tid % 24) * 8;      // 8 floats/thread (2 x float4)
    const float* wsrc = &g_whhT[nh * 192];

    wmma::fragment<wmma::accumulator, 16, 16, 8, float> c[4];
    #pragma unroll
    for (int m = 0; m < 4; ++m) wmma::fill_fragment(c[m], 0.f);

    // preload slice 0
    float4 v0 = *(const float4*)&wsrc[srow * 384 + scol];
    float4 v1 = *(const float4*)&wsrc[srow * 384 + scol + 4];
    *(float4*)&s_b[0][srow * LDB2 + scol]     = v0;
    *(float4*)&s_b[0][srow * LDB2 + scol + 4] = v1;
    __syncthreads();

    #pragma unroll 1
    for (int it = 0; it < 8; ++it) {
        const int buf = it & 1;
        if (it < 7) {   // prefetch next 16-row slice (hidden under MMAs)
            v0 = *(const float4*)&wsrc[((it + 1) * 16 + srow) * 384 + scol];
            v1 = *(const float4*)&wsrc[((it + 1) * 16 + srow) * 384 + scol + 4];
        }
        #pragma unroll
        for (int kk2 = 0; kk2 < 2; ++kk2) {
            wmma::fragment<wmma::matrix_b, 16, 16, 8, wmma::precision::tf32, wmma::row_major> bf;
            wmma::load_matrix_sync(bf, &s_b[buf][kk2 * 8 * LDB2] + wid * 16, LDB2);
            #pragma unroll
            for (int m = 0; m < 4; ++m) {
                wmma::fragment<wmma::matrix_a, 16, 16, 8, wmma::precision::tf32, wmma::row_major> a;
                wmma::load_matrix_sync(a, s_h + (m * 16) * LDA + (it * 16 + kk2 * 8), LDA);
                wmma::mma_sync(c[m], a, bf, c[m]);
            }
        }
        if (it < 7) {
            // write NEXT slice into the other buffer; safe: that buffer was
            // last read in iteration it-1, all warps past it (sync below).
            *(float4*)&s_b[buf ^ 1][srow * LDB2 + scol]     = v0;
            *(float4*)&s_b[buf ^ 1][srow * LDB2 + scol + 4] = v1;
            __syncthreads();
        }
    }

    float* ghb = &g_gh[b * 64 * 384 + nh * 192];
    #pragma unroll
    for (int m = 0; m < 4; ++m)
        wmma::store_matrix_sync(ghb + (m * 16) * 384 + wid * 16, c[m],
                                384, wmma::mem_row_major);
}

// ================= epi: fused GRU gates (flat, full occupancy) ===============
__global__ void __launch_bounds__(512) epi_kernel(const float* __restrict__ b_hh,
                                                  float* __restrict__ out, int step) {
    const int idx = blockIdx.x * 512 + threadIdx.x;
    const int d = idx & 127;
    const int n = (idx >> 7) & 63;
    const int b = idx >> 13;
    const int node = b * TOPK + n;
    const int rel = g_r[step][node];
    const int p   = g_p[step][node];
    const float* gi  = &g_relgi[rel * 384];
    const float* ghp = &g_gh[node * 384];
    float hprev = out[OFF_TE + ((b * 3 + (step - 1)) * 64 + p) * 128 + d];
    float hr = ghp[d]       + b_hh[d];
    float hz = ghp[128 + d] + b_hh[128 + d];
    float hn = ghp[256 + d] + b_hh[256 + d];
    float rg = sig_hw(gi[d] + hr);
    float z  = sig_hw(gi[128 + d] + hz);
    float nn = tanh_hw(fmaf(rg, hn, gi[256 + d]));
    out[OFF_TE + ((b * 3 + step) * 64 + n) * 128 + d] = fmaf(z, hprev - nn, nn);
}

// ================= launch =====================================================
extern "C" void kernel_launch(void* const* d_in, const int* in_sizes, int n_in,
                              void* d_out, int out_size) {
    (void)in_sizes; (void)n_in; (void)out_size;
    const int*   qh      = (const int*)d_in[0];
    const int2*  edge    = (const int2*)d_in[1];
    const int*   sup     = (const int*)d_in[2];
    const float* cosm    = (const float*)d_in[3];
    const float* rel_emb = (const float*)d_in[4];
    const float* wih     = (const float*)d_in[5];
    const float* whh     = (const float*)d_in[6];
    const float* bih     = (const float*)d_in[7];
    const float* bhh     = (const float*)d_in[8];
    float* out = (float*)d_out;

    k1_kernel<<<106, 512>>>(wih, whh, cosm, sup);
    k2_kernel<<<609, 128>>>(rel_emb, bih, edge, qh, out);
    k3_kernel<<<4352, 512>>>(edge, bhh, out);
    gemm_kernel<<<dim3(2, BATCH), 384>>>(out, 1);
    xbig_kernel<<<BATCH, 512>>>(edge, out, 2);   // independent of epi(1)
    epi_kernel<<<4096, 512>>>(bhh, out, 1);
    gemm_kernel<<<dim3(2, BATCH), 384>>>(out, 2);
    epi_kernel<<<4096, 512>>>(bhh, out, 2);
}

// round 17
// speedup vs baseline: 1.0300x; 1.0300x over previous
#include <cuda_runtime.h>
#include <cuda_bf16.h>
#include <mma.h>
#include <math.h>

using namespace nvcuda;

#define BATCH   256
#define NEI     128
#define NRELS   5000
#define NSUP    32
#define DIM     128
#define TOPK    64
#define NCAND   8192

#define OFF_TN  0
#define OFF_TE  49152
#define OFF_PI  6340608
#define OFF_PN  6389760
#define OFF_AR  6438912

typedef unsigned long long ull;
typedef unsigned int u32;

__device__ float g_best[NRELS];
__device__ u32   g_rank[NRELS];
__device__ float g_relgi[NRELS * 384];
__device__ ull   g_w2ih[128 * 384];              // dup-pair W_ih for relgi
__device__ float g_whhT[128 * 384];              // W_hh^T k-major, tf32-rounded
__device__ float g_gh[BATCH * TOPK * 384];       // GEMM output scratch
__device__ int   g_e[3][BATCH * TOPK];
__device__ int   g_r[3][BATCH * TOPK];
__device__ int   g_p[3][BATCH * TOPK];

__device__ __forceinline__ ull f2pack(float lo, float hi) {
    ull d; asm("mov.b64 %0, {%1, %2};" : "=l"(d) : "f"(lo), "f"(hi)); return d;
}
__device__ __forceinline__ ull f2fma(ull a, ull b, ull c) {
    ull d; asm("fma.rn.f32x2 %0, %1, %2, %3;" : "=l"(d) : "l"(a), "l"(b), "l"(c)); return d;
}
__device__ __forceinline__ u32 ord32(float s) {
    u32 u = __float_as_uint(s);
    return (u & 0x80000000u) ? ~u : (u | 0x80000000u);
}
__device__ __forceinline__ float tanh_hw(float x) {
    float y; asm("tanh.approx.f32 %0, %1;" : "=f"(y) : "f"(x)); return y;
}
__device__ __forceinline__ float sig_hw(float x) {
    return fmaf(tanh_hw(0.5f * x), 0.5f, 0.5f);
}

#define SHN 20
#define LDA 132
#define LDB2 200   // 192-col B slice + pad

// ================= expand_big body (templated block size) ====================
template <int NT>
__device__ __forceinline__ void expand_big_body(const int2* __restrict__ edge,
                                                float* __restrict__ out,
                                                int step, int b) {
    constexpr int CHUNK = (NCAND + NT - 1) / NT;
    constexpr int NW = NT / 32;
    __shared__ int s_cur[TOPK];
    __shared__ u32 s_p13[NW], s_q13[NW];
    __shared__ u32 s_bp, s_bq;
    __shared__ u32 wkeys[TOPK];
    __shared__ u32 s_wn;

    const int tid = threadIdx.x;
    const int wid = tid >> 5, lane = tid & 31;

    if (tid < TOPK) s_cur[tid] = g_e[step - 1][b * TOPK + tid];
    if (tid == 0) s_wn = 0;
    __syncthreads();

    u32 myk[CHUNK];
    #pragma unroll
    for (int m = 0; m < CHUNK; ++m) {
        int i = tid + m * NT;
        if (i < NCAND) {
            int c = i >> 7, n = i & 127;
            int2 pr = __ldg(&edge[(long long)s_cur[c] * NEI + n]);
            myk[m] = (g_rank[pr.y] << 13) | (u32)i;
        } else {
            myk[m] = 0xFFFFFFFFu;   // dummy: never counted, never wins
        }
    }

    u32 K = 0;
    #pragma unroll 1
    for (int shift = 24; shift >= 0; shift -= 2) {
        u32 X1 = K | (1u << shift), X2 = K | (2u << shift), X3 = K | (3u << shift);
        u32 c1 = 0, c2 = 0, c3 = 0;
        #pragma unroll
        for (int m = 0; m < CHUNK; ++m) {
            u32 k0 = myk[m];
            c1 += (k0 < X1); c2 += (k0 < X2); c3 += (k0 < X3);
        }
        u32 p = c1 | (c2 << 16);
        u32 q = c3;
        p = __reduce_add_sync(0xffffffffu, p);
        q = __reduce_add_sync(0xffffffffu, q);
        if (lane == 0) { s_p13[wid] = p; s_q13[wid] = q; }
        __syncthreads();
        if (tid < 32) {
            u32 vp = (tid < NW) ? s_p13[tid] : 0u;
            u32 vq = (tid < NW) ? s_q13[tid] : 0u;
            vp = __reduce_add_sync(0xffffffffu, vp);
            vq = __reduce_add_sync(0xffffffffu, vq);
            if (tid == 0) { s_bp = vp; s_bq = vq; }
        }
        __syncthreads();
        u32 n1 = s_bp & 0xffffu, n2 = s_bp >> 16, n3 = s_bq;
        u32 t = (n1 < TOPK) ? ((n2 < TOPK) ? ((n3 < TOPK) ? 3u : 2u) : 1u) : 0u;
        K |= t << shift;
        __syncthreads();
    }

    #pragma unroll
    for (int m = 0; m < CHUNK; ++m) {
        if (myk[m] <= K) {
            u32 p = atomicAdd(&s_wn, 1u);
            wkeys[p] = myk[m];
        }
    }
    __syncthreads();

    if (tid < TOPK) {
        u32 my = wkeys[tid];
        int rank = 0;
        #pragma unroll 8
        for (int t = 0; t < TOPK; ++t) rank += (wkeys[t] < my);
        int i = my & (NCAND - 1);
        int c = i >> 7, n = i & 127;
        int ent = s_cur[c];
        int2 pr = __ldg(&edge[(long long)ent * NEI + n]);
        int j = rank;
        int gidx = b * TOPK + j;
        g_e[step][gidx] = pr.x;
        g_r[step][gidx] = pr.y;
        g_p[step][gidx] = c;
        out[OFF_TN + b * 192 + step * 64 + j] = (float)pr.x;
        if (step == 1) {
            out[OFF_PI + b * 192 + j]       = (float)c;
            out[OFF_PN + b * 192 + 64 + j]  = (float)g_e[0][b * TOPK + c];
            out[OFF_AR + b * 192 + j]       = (float)g_r[0][b * TOPK + c];
        } else {
            out[OFF_PI + b * 192 + 64 + j]  = (float)c;
            out[OFF_PN + b * 192 + 128 + j] = (float)g_e[1][b * TOPK + c];
            out[OFF_AR + b * 192 + 64 + j]  = (float)g_r[1][b * TOPK + c];
            out[OFF_AR + b * 192 + 128 + j] = (float)pr.y;
        }
    }
}

// ================= gemm body (R15-proven): 64 nodes x 192 cols ===============
__device__ __forceinline__ void gemm_body(const float* __restrict__ out,
                                          int step, int nh, int b) {
    __shared__ __align__(16) float s_h[64 * LDA];    // 33.8 KB
    __shared__ __align__(16) float s_b[8 * LDB2];    // 6.25 KB
    __shared__ int s_p[64];

    const int tid = threadIdx.x;
    if (tid < 64) s_p[tid] = g_p[step][b * TOPK + tid];
    __syncthreads();
    const float* te_prev = &out[OFF_TE + (b * 3 + (step - 1)) * 64 * 128];
    for (int idx = tid; idx < 64 * 128; idx += 384) {
        int n = idx >> 7, d = idx & 127;
        s_h[n * LDA + d] = wmma::__float_to_tf32(te_prev[s_p[n] * 128 + d]);
    }

    const int wid = tid >> 5;
    const int srow = tid / 48;            // staging row 0..7
    const int scol = (tid % 48) * 4;      // 4 floats/thread, 192 per row
    const float* wsrc = &g_whhT[nh * 192];

    wmma::fragment<wmma::accumulator, 16, 16, 8, float> c[4];
    #pragma unroll
    for (int m = 0; m < 4; ++m) wmma::fill_fragment(c[m], 0.f);

    float4 v = *(const float4*)&wsrc[srow * 384 + scol];
    #pragma unroll 1
    for (int kk = 0; kk < 16; ++kk) {
        __syncthreads();                   // prior readers of s_b done
        *(float4*)&s_b[srow * LDB2 + scol] = v;
        if (kk < 15)
            v = *(const float4*)&wsrc[((kk + 1) * 8 + srow) * 384 + scol];
        __syncthreads();

        wmma::fragment<wmma::matrix_b, 16, 16, 8, wmma::precision::tf32, wmma::row_major> bf;
        wmma::load_matrix_sync(bf, s_b + wid * 16, LDB2);
        #pragma unroll
        for (int m = 0; m < 4; ++m) {
            wmma::fragment<wmma::matrix_a, 16, 16, 8, wmma::precision::tf32, wmma::row_major> a;
            wmma::load_matrix_sync(a, s_h + (m * 16) * LDA + kk * 8, LDA);
            wmma::mma_sync(c[m], a, bf, c[m]);
        }
    }

    float* ghb = &g_gh[b * 64 * 384 + nh * 192];
    #pragma unroll
    for (int m = 0; m < 4; ++m)
        wmma::store_matrix_sync(ghb + (m * 16) * 384 + wid * 16, c[m],
                                384, wmma::mem_row_major);
}

// ================= K1: weight prep || best ===================================
__global__ void __launch_bounds__(512) k1_kernel(const float* __restrict__ wih,
                                                 const float* __restrict__ whh,
                                                 const float* __restrict__ cosm,
                                                 const int* __restrict__ sup) {
    const int bid = blockIdx.x, tid = threadIdx.x;
    if (bid < 96) {
        int idx = bid * 512 + tid;
        int j = idx / 128, k = idx % 128;
        float a = wih[idx];
        g_w2ih[k * 384 + j] = f2pack(a, a);
        g_whhT[k * 384 + j] = wmma::__float_to_tf32(whh[idx]);
    } else {
        __shared__ int ss[NSUP];
        if (tid < NSUP) ss[tid] = sup[tid];
        __syncthreads();
        int r = (bid - 96) * 512 + tid;
        if (r < NRELS) {
            float m = -3.4e38f;
            #pragma unroll
            for (int s = 0; s < NSUP; ++s)
                m = fmaxf(m, cosm[(long long)ss[s] * NRELS + r]);
            g_best[r] = m;
        }
    }
}

// ================= K2: relgi || rank || expand0 (128-thread blocks) ==========
__global__ void __launch_bounds__(128) k2_kernel(const float* __restrict__ rel_emb,
                                                 const float* __restrict__ b_ih,
                                                 const int2* __restrict__ edge,
                                                 const int* __restrict__ query_head,
                                                 float* __restrict__ out) {
    const int bid = blockIdx.x, tid = threadIdx.x;
    if (bid < 313) {
        __shared__ __align__(16) float s_x[128 * SHN];
        const int rb = bid * 16;
        const int d = tid;
        #pragma unroll
        for (int n = 0; n < 16; ++n) {
            int r = rb + n;
            s_x[d * SHN + n] = (r < NRELS) ? __ldg(&rel_emb[r * 128 + d]) : 0.f;
        }
        __syncthreads();
        ull aR[8], aZ[8], aN[8];
        float br = b_ih[d], bz = b_ih[128 + d], bn = b_ih[256 + d];
        #pragma unroll
        for (int m = 0; m < 8; ++m) {
            aR[m] = f2pack(br, br); aZ[m] = f2pack(bz, bz); aN[m] = f2pack(bn, bn);
        }
        const ull* wt = g_w2ih;
        #pragma unroll 4
        for (int k = 0; k < 128; ++k) {
            ull wr2 = __ldg(&wt[k * 384 + d]);
            ull wz2 = __ldg(&wt[k * 384 + 128 + d]);
            ull wn2 = __ldg(&wt[k * 384 + 256 + d]);
            const ulonglong2* row = (const ulonglong2*)&s_x[k * SHN];
            ulonglong2 h0 = row[0], h1 = row[1], h2 = row[2], h3 = row[3];
            aR[0] = f2fma(wr2, h0.x, aR[0]); aR[1] = f2fma(wr2, h0.y, aR[1]);
            aR[2] = f2fma(wr2, h1.x, aR[2]); aR[3] = f2fma(wr2, h1.y, aR[3]);
            aR[4] = f2fma(wr2, h2.x, aR[4]); aR[5] = f2fma(wr2, h2.y, aR[5]);
            aR[6] = f2fma(wr2, h3.x, aR[6]); aR[7] = f2fma(wr2, h3.y, aR[7]);
            aZ[0] = f2fma(wz2, h0.x, aZ[0]); aZ[1] = f2fma(wz2, h0.y, aZ[1]);
            aZ[2] = f2fma(wz2, h1.x, aZ[2]); aZ[3] = f2fma(wz2, h1.y, aZ[3]);
            aZ[4] = f2fma(wz2, h2.x, aZ[4]); aZ[5] = f2fma(wz2, h2.y, aZ[5]);
            aZ[6] = f2fma(wz2, h3.x, aZ[6]); aZ[7] = f2fma(wz2, h3.y, aZ[7]);
            aN[0] = f2fma(wn2, h0.x, aN[0]); aN[1] = f2fma(wn2, h0.y, aN[1]);
            aN[2] = f2fma(wn2, h1.x, aN[2]); aN[3] = f2fma(wn2, h1.y, aN[3]);
            aN[4] = f2fma(wn2, h2.x, aN[4]); aN[5] = f2fma(wn2, h2.y, aN[5]);
            aN[6] = f2fma(wn2, h3.x, aN[6]); aN[7] = f2fma(wn2, h3.y, aN[7]);
        }
        #pragma unroll
        for (int m = 0; m < 8; ++m) {
            float2 vr = *(float2*)&aR[m], vz = *(float2*)&aZ[m], vn = *(float2*)&aN[m];
            int r0 = rb + 2 * m, r1 = r0 + 1;
            if (r0 < NRELS) {
                g_relgi[r0 * 384 + d] = vr.x;
                g_relgi[r0 * 384 + 128 + d] = vz.x;
                g_relgi[r0 * 384 + 256 + d] = vn.x;
            }
            if (r1 < NRELS) {
                g_relgi[r1 * 384 + d] = vr.y;
                g_relgi[r1 * 384 + 128 + d] = vz.y;
                g_relgi[r1 * 384 + 256 + d] = vn.y;
            }
        }
    } else if (bid < 353) {
        __shared__ float tile[128];
        const int r = (bid - 313) * 128 + tid;
        const float mine = (r < NRELS) ? g_best[r] : 3.4e38f;
        u32 cnt = 0;
        for (int base = 0; base < NRELS; base += 128) {
            int t = base + tid;
            tile[tid] = (t < NRELS) ? g_best[t] : -3.4e38f;
            __syncthreads();
            int lim = NRELS - base; if (lim > 128) lim = 128;
            #pragma unroll 8
            for (int u = 0; u < lim; ++u) cnt += (tile[u] > mine);
            __syncthreads();
        }
        if (r < NRELS) g_rank[r] = cnt;
    } else {
        __shared__ __align__(16) ull keys[128];
        __shared__ int s_ent;
        const int b = bid - 353;
        const int i = tid;
        if (i == 0) s_ent = query_head[b];
        __syncthreads();
        const int ent = s_ent;
        int2 pr = __ldg(&edge[(long long)ent * NEI + i]);
        ull mykey = ((ull)ord32(g_best[pr.y]) << 32) | (u32)(127 - i);
        keys[i] = mykey;
        __syncthreads();
        int rank = 0;
        #pragma unroll 8
        for (int t = 0; t < 128; ++t) rank += (keys[t] > mykey);
        if (rank < TOPK) {
            int j = rank;
            int gidx = b * TOPK + j;
            g_e[0][gidx] = pr.x;
            g_r[0][gidx] = pr.y;
            g_p[0][gidx] = 0;
            out[OFF_TN + b * 192 + j] = (float)pr.x;
            out[OFF_PN + b * 192 + j] = (float)ent;
            out[OFF_PI + b * 192 + 128 + j] = (float)j;
        }
    }
}

// ================= K3: expand_big(1) || gru1 (hw-tanh) =======================
__global__ void __launch_bounds__(512) k3_kernel(const int2* __restrict__ edge,
                                                 const float* __restrict__ b_hh,
                                                 float* __restrict__ out) {
    const int bid = blockIdx.x;
    if (bid < 256) {
        expand_big_body<512>(edge, out, 1, bid);
    } else {
        const int idx = (bid - 256) * 512 + threadIdx.x;
        const int d = idx & 127;
        const int k = (idx >> 7) & 63;
        const int b = idx >> 13;
        const int r = g_r[0][b * TOPK + k];
        const float* gi = &g_relgi[r * 384];
        float hr = b_hh[d], hz = b_hh[128 + d], hn = b_hh[256 + d];
        float rg = sig_hw(gi[d] + hr);
        float z  = sig_hw(gi[128 + d] + hz);
        float nn = tanh_hw(fmaf(rg, hn, gi[256 + d]));
        out[OFF_TE + ((b * 3 + 0) * 64 + k) * 128 + d] = (1.f - z) * nn;
    }
}

// ================= GX1: gemm(1) [0,512) || expand_big(2) [512,768) ===========
__global__ void __launch_bounds__(384) gx1_kernel(const int2* __restrict__ edge,
                                                  const float* __restrict__ out_c,
                                                  float* __restrict__ out) {
    const int bid = blockIdx.x;
    if (bid < 512) {
        gemm_body(out_c, 1, bid & 1, bid >> 1);
    } else {
        expand_big_body<384>(edge, out, 2, bid - 512);
    }
}

// ================= gemm standalone (step 2) ==================================
__global__ void __launch_bounds__(384) gemm_kernel(const float* __restrict__ out, int step) {
    gemm_body(out, step, blockIdx.x, blockIdx.y);
}

// ================= epi: fused GRU gates (flat, full occupancy) ===============
__global__ void __launch_bounds__(512) epi_kernel(const float* __restrict__ b_hh,
                                                  float* __restrict__ out, int step) {
    const int idx = blockIdx.x * 512 + threadIdx.x;
    const int d = idx & 127;
    const int n = (idx >> 7) & 63;
    const int b = idx >> 13;
    const int node = b * TOPK + n;
    const int rel = g_r[step][node];
    const int p   = g_p[step][node];
    const float* gi  = &g_relgi[rel * 384];
    const float* ghp = &g_gh[node * 384];
    float hprev = out[OFF_TE + ((b * 3 + (step - 1)) * 64 + p) * 128 + d];
    float hr = ghp[d]       + b_hh[d];
    float hz = ghp[128 + d] + b_hh[128 + d];
    float hn = ghp[256 + d] + b_hh[256 + d];
    float rg = sig_hw(gi[d] + hr);
    float z  = sig_hw(gi[128 + d] + hz);
    float nn = tanh_hw(fmaf(rg, hn, gi[256 + d]));
    out[OFF_TE + ((b * 3 + step) * 64 + n) * 128 + d] = fmaf(z, hprev - nn, nn);
}

// ================= launch =====================================================
extern "C" void kernel_launch(void* const* d_in, const int* in_sizes, int n_in,
                              void* d_out, int out_size) {
    (void)in_sizes; (void)n_in; (void)out_size;
    const int*   qh      = (const int*)d_in[0];
    const int2*  edge    = (const int2*)d_in[1];
    const int*   sup     = (const int*)d_in[2];
    const float* cosm    = (const float*)d_in[3];
    const float* rel_emb = (const float*)d_in[4];
    const float* wih     = (const float*)d_in[5];
    const float* whh     = (const float*)d_in[6];
    const float* bih     = (const float*)d_in[7];
    const float* bhh     = (const float*)d_in[8];
    float* out = (float*)d_out;

    k1_kernel<<<106, 512>>>(wih, whh, cosm, sup);
    k2_kernel<<<609, 128>>>(rel_emb, bih, edge, qh, out);
    k3_kernel<<<4352, 512>>>(edge, bhh, out);
    gx1_kernel<<<768, 384>>>(edge, out, out);     // gemm(1) || xbig(2)
    epi_kernel<<<4096, 512>>>(bhh, out, 1);
    gemm_kernel<<<dim3(2, BATCH), 384>>>(out, 2);
    epi_kernel<<<4096, 512>>>(bhh, out, 2);
}